// round 11
// baseline (speedup 1.0000x reference)
#include <cuda_runtime.h>
#include <stdint.h>

#define BATCH 64
#define SEQ   2048
#define D     256
#define HALF  128
#define CHUNK 64
#define NCHUNK 32

#define KREG 176
#define KSM  80                            // k = 176..255 in smem
#define NGR  (KREG / 4)                    // 44 reg groups
#define NGS  (KSM / 4)                     // 20 smem groups
#define WSTRIDE 84                         // 21 float4/col, phase 5j%8: conflict-free

// ---- shared memory layout (float offsets) ----
#define OFF_RING0 0
#define OFF_RING1 8192
#define OFF_WST   16384                    // [128][84] = 10752
#define OFF_HBUF  (16384 + 10752)          // 27136: [2][256] = 512
#define OFF_AS    (27136 + 512)            // 27648: [64][36] = 2304
#define OFF_BS    (27648 + 2304)           // 29952: [32][64] = 2048
#define SMEM_FLOATS (29952 + 2048)         // 32000
#define MBAR_BYTE (SMEM_FLOATS * 4)        // 128000 (8-aligned)
#define SMEM_BYTES (MBAR_BYTE + 32)

// named barriers: 1 = scan h rendezvous; 2,3 = ring empty; 4,5 = ring full; 6 = gemm
#define NB_H      1
#define NB_EMPTY(c) (2 + ((c) & 1))
#define NB_FULL(c)  (4 + ((c) & 1))
#define NB_GEMM   6

__device__ __forceinline__ uint32_t smem_u32(const void* p)
{
    uint32_t a;
    asm("{ .reg .u64 t; cvta.to.shared.u64 t, %1; cvt.u32.u64 %0, t; }"
        : "=r"(a) : "l"(p));
    return a;
}
__device__ __forceinline__ void nbar_sync(int id, int cnt)
{
    asm volatile("bar.sync %0, %1;" :: "r"(id), "r"(cnt) : "memory");
}
__device__ __forceinline__ void nbar_arrive(int id, int cnt)
{
    asm volatile("bar.arrive %0, %1;" :: "r"(id), "r"(cnt) : "memory");
}
__device__ __forceinline__ uint32_t mapa_u32(uint32_t local, uint32_t rank)
{
    uint32_t r;
    asm("mapa.shared::cluster.u32 %0, %1, %2;" : "=r"(r) : "r"(local), "r"(rank));
    return r;
}
__device__ __forceinline__ void mbar_init(uint32_t addr, uint32_t cnt)
{
    asm volatile("mbarrier.init.shared.b64 [%0], %1;" :: "r"(addr), "r"(cnt) : "memory");
}
// release at cluster scope: orders this thread's prior remote store
__device__ __forceinline__ void mbar_arrive_remote_rel(uint32_t remote_addr)
{
    asm volatile("mbarrier.arrive.release.cluster.shared::cluster.b64 _, [%0];"
                 :: "r"(remote_addr) : "memory");
}
__device__ __forceinline__ void st_remote_f32(uint32_t remote_addr, float v)
{
    asm volatile("st.shared::cluster.f32 [%0], %1;"
                 :: "r"(remote_addr), "f"(v) : "memory");
}
__device__ __forceinline__ void mbar_wait_parity_acq(uint32_t addr, uint32_t parity)
{
    uint32_t done;
    asm volatile(
        "{\n\t.reg .pred p;\n\t"
        "mbarrier.try_wait.parity.acquire.cluster.shared::cta.b64 p, [%1], %2;\n\t"
        "selp.b32 %0, 1, 0, p;\n\t}"
        : "=r"(done) : "r"(addr), "r"(parity) : "memory");
    while (!done) {
        asm volatile(
            "{\n\t.reg .pred p;\n\t"
            "mbarrier.try_wait.parity.acquire.cluster.shared::cta.b64 p, [%1], %2, 0x989680;\n\t"
            "selp.b32 %0, 1, 0, p;\n\t}"
            : "=r"(done) : "r"(addr), "r"(parity) : "memory");
    }
}
__device__ __forceinline__ void cluster_sync_all()
{
    asm volatile("barrier.cluster.arrive.aligned;" ::: "memory");
    asm volatile("barrier.cluster.wait.aligned;" ::: "memory");
}

// ---------------------------------------------------------------------------
// Bit-exact replica of XLA's EmitFastTanh (Eigen fast tanh, FMA variant).
// ---------------------------------------------------------------------------
__device__ __forceinline__ float xla_tanh(float x)
{
    const float kClamp = 7.99881172180175781f;
    const float kTiny  = 0.0004f;
    const float a1  = 4.89352455891786e-03f;
    const float a3  = 6.37261928875436e-04f;
    const float a5  = 1.48572235717979e-05f;
    const float a7  = 5.12229709037114e-08f;
    const float a9  = -8.60467152213735e-11f;
    const float a11 = 2.00018790482477e-13f;
    const float a13 = -2.76076847742355e-16f;
    const float b0  = 4.89352518554385e-03f;
    const float b2  = 2.26843463243900e-03f;
    const float b4  = 1.18534705686654e-04f;
    const float b6  = 1.19825839466702e-06f;

    float ax = fabsf(x);
    float xc = fminf(fmaxf(x, -kClamp), kClamp);
    float x2 = __fmul_rn(xc, xc);

    float p = __fmaf_rn(x2, a13, a11);
    p = __fmaf_rn(x2, p, a9);
    p = __fmaf_rn(x2, p, a7);
    p = __fmaf_rn(x2, p, a5);
    p = __fmaf_rn(x2, p, a3);
    p = __fmaf_rn(x2, p, a1);
    p = __fmul_rn(xc, p);

    float q = __fmaf_rn(x2, b6, b4);
    q = __fmaf_rn(x2, q, b2);
    q = __fmaf_rn(x2, q, b0);

    float r = __fdiv_rn(p, q);
    return (ax < kTiny) ? x : r;
}

// ---------------------------------------------------------------------------
// GEMM producer half (threads 0..127, warps 0-3, low arbiter priority):
// zx chunks (64 steps x this rank's 128 cols) into a 2-slot smem ring.
// Bit-exact: single fp32 accumulator, ascending k, fused FMA.
// ---------------------------------------------------------------------------
__device__ void gemm_half(
    float* smf, int rank, int bb,
    const float* __restrict__ input,
    const float* __restrict__ Wx,
    const float* __restrict__ b_h,
    const float* __restrict__ b_x)
{
    const int tid = threadIdx.x;      // 0..127
    const int tx = tid & 15;
    const int ty = tid >> 4;
    float* As = smf + OFF_AS;         // [64][36]
    float* Bs = smf + OFF_BS;         // [32][64]

    float bias[2][4];
#pragma unroll
    for (int nh = 0; nh < 2; ++nh)
#pragma unroll
        for (int jj = 0; jj < 4; ++jj) {
            int g = rank * HALF + nh * 64 + tx * 4 + jj;
            bias[nh][jj] = __fadd_rn(b_h[g], b_x[g]);
        }

    const float* Ab = input + (size_t)bb * SEQ * D;

#pragma unroll 1
    for (int c = 0; c < NCHUNK; ++c) {
        nbar_sync(NB_EMPTY(c), 256);
        float* ring = smf + ((c & 1) ? OFF_RING1 : OFF_RING0);

#pragma unroll 1
        for (int nh = 0; nh < 2; ++nh) {
            const int n0 = rank * HALF + nh * 64;
            float acc[32];
#pragma unroll
            for (int i = 0; i < 32; ++i) acc[i] = 0.f;

#pragma unroll 1
            for (int kc = 0; kc < D; kc += 32) {
                nbar_sync(NB_GEMM, 128);
#pragma unroll
                for (int l = 0; l < 4; ++l) {
                    int i = tid + l * 128;
                    int r = i >> 3, col = (i & 7) << 2;
                    float4 v = __ldcs((const float4*)(
                        Ab + (size_t)(c * CHUNK + r) * D + kc + col));
                    As[r * 36 + col + 0] = v.x; As[r * 36 + col + 1] = v.y;
                    As[r * 36 + col + 2] = v.z; As[r * 36 + col + 3] = v.w;
                }
#pragma unroll
                for (int l = 0; l < 4; ++l) {
                    int i = tid + l * 128;
                    int kr = i >> 4, n4 = (i & 15) << 2;
                    *(float4*)(Bs + kr * 64 + n4) =
                        *(const float4*)(Wx + (kc + kr) * D + n0 + n4);
                }
                nbar_sync(NB_GEMM, 128);
#pragma unroll
                for (int k = 0; k < 32; ++k) {
                    float4 b4 = *(const float4*)(Bs + k * 64 + (tx << 2));
#pragma unroll
                    for (int i = 0; i < 8; ++i) {
                        float a = As[(ty * 8 + i) * 36 + k];
                        acc[i * 4 + 0] = __fmaf_rn(a, b4.x, acc[i * 4 + 0]);
                        acc[i * 4 + 1] = __fmaf_rn(a, b4.y, acc[i * 4 + 1]);
                        acc[i * 4 + 2] = __fmaf_rn(a, b4.z, acc[i * 4 + 2]);
                        acc[i * 4 + 3] = __fmaf_rn(a, b4.w, acc[i * 4 + 3]);
                    }
                }
            }
#pragma unroll
            for (int i = 0; i < 8; ++i) {
                float4 o;
                o.x = __fadd_rn(acc[i * 4 + 0], bias[nh][0]);
                o.y = __fadd_rn(acc[i * 4 + 1], bias[nh][1]);
                o.z = __fadd_rn(acc[i * 4 + 2], bias[nh][2]);
                o.w = __fadd_rn(acc[i * 4 + 3], bias[nh][3]);
                *(float4*)(ring + (ty * 8 + i) * HALF + nh * 64 + (tx << 2)) = o;
            }
        }
        nbar_arrive(NB_FULL(c), 256);
    }
}

// ---------------------------------------------------------------------------
// Cluster kernel: 128 CTAs = 64 clusters of 2 (one batch row per cluster).
// Scan half = threads 128..255 (warps 4-7, high arbiter priority), one column
// per thread (this rank's 128 columns). Peer h-half pushed via DSMEM with
// release-arrive / acquire-wait mbarrier pairs. Bit-exact chains throughout.
// ---------------------------------------------------------------------------
__global__ __launch_bounds__(256, 1) __cluster_dims__(2, 1, 1)
void rnn_cluster_kernel(
    const float* __restrict__ input,
    const float* __restrict__ h0,
    const float* __restrict__ Wh,
    const float* __restrict__ Wx,
    const float* __restrict__ b_h,
    const float* __restrict__ b_x,
    float* __restrict__ y,
    float* __restrict__ hfin)
{
    extern __shared__ float smf[];
    const uint32_t sbase = smem_u32(smf);
    const int tid = threadIdx.x;
    const int bb  = blockIdx.x >> 1;
    uint32_t rank;
    asm("mov.u32 %0, %%cluster_ctarank;" : "=r"(rank));
    const uint32_t peer = rank ^ 1u;

    const uint32_t mbar0 = sbase + MBAR_BYTE;
    const uint32_t mbar1 = sbase + MBAR_BYTE + 8;

    if (tid == 0) {
        mbar_init(mbar0, HALF);
        mbar_init(mbar1, HALF);
    }
    __syncthreads();
    cluster_sync_all();                       // mbar init visible cluster-wide

    if (tid < 128) {
        gemm_half(smf, (int)rank, bb, input, Wx, b_h, b_x);
    } else {
        // ================= scan half =================
        const int jl   = tid - 128;           // 0..127
        const int gcol = (int)rank * HALF + jl;
        const int pcol = (int)peer * HALF + jl;

        // release both ring slots so GEMM starts during our setup
        nbar_arrive(2, 256);
        nbar_arrive(3, 256);

        float w[KREG];
#pragma unroll
        for (int kk = 0; kk < KREG; ++kk)
            w[kk] = Wh[kk * D + gcol];

#pragma unroll
        for (int i = 0; i < KSM; ++i)
            smf[OFF_WST + jl * WSTRIDE + i] = Wh[(KREG + i) * D + gcol];

        smf[OFF_HBUF + gcol] = h0[bb * D + gcol];   // own half of h0
        smf[OFF_HBUF + pcol] = h0[bb * D + pcol];   // peer half, local copy

        const uint32_t hb_r0 = mapa_u32(sbase + (OFF_HBUF + 0 * D + gcol) * 4, peer);
        const uint32_t hb_r1 = mapa_u32(sbase + (OFF_HBUF + 1 * D + gcol) * 4, peer);
        const uint32_t mb_r0 = mapa_u32(mbar0, peer);
        const uint32_t mb_r1 = mapa_u32(mbar1, peer);

        // prime step 0: local rendezvous credit + peer mbar phase 0
        nbar_arrive(NB_H, 256);
        mbar_arrive_remote_rel(mb_r0);

        const float4* wt4 = (const float4*)(smf + OFF_WST + jl * WSTRIDE);
        float* yrow = y + (size_t)bb * SEQ * D + gcol;
        int cur = 0;
        float v = 0.f;

#pragma unroll 1
        for (int c = 0; c < NCHUNK; ++c) {
            nbar_sync(NB_FULL(c), 256);        // zx chunk ready in ring
            const float* ring = smf + ((c & 1) ? OFF_RING1 : OFF_RING0);

#pragma unroll 1
            for (int ti = 0; ti < CHUNK; ++ti) {
                const int t = c * CHUNK + ti;
                float zx = ring[ti * HALF + jl];

                const float4* h4 = (const float4*)(smf + OFF_HBUF + cur * D);
                const uint32_t mb_w = (t & 1) ? mbar1 : mbar0;
                const uint32_t par  = (t >> 1) & 1;
                float acc = 0.f;

                nbar_sync(NB_H, 256);          // own-half h_t ready locally
                if (rank) mbar_wait_parity_acq(mb_w, par);   // peer = k 0..127

                // groups 0..31 : k = 0..127 (register weights)
#pragma unroll
                for (int g = 0; g < 32; ++g) {
                    float4 hv = h4[g];
                    acc = __fmaf_rn(hv.x, w[4 * g + 0], acc);
                    acc = __fmaf_rn(hv.y, w[4 * g + 1], acc);
                    acc = __fmaf_rn(hv.z, w[4 * g + 2], acc);
                    acc = __fmaf_rn(hv.w, w[4 * g + 3], acc);
                }

                if (!rank) mbar_wait_parity_acq(mb_w, par);  // peer = k 128..255

                // groups 32..43 : k = 128..175 (register weights)
#pragma unroll
                for (int g = 32; g < NGR; ++g) {
                    float4 hv = h4[g];
                    acc = __fmaf_rn(hv.x, w[4 * g + 0], acc);
                    acc = __fmaf_rn(hv.y, w[4 * g + 1], acc);
                    acc = __fmaf_rn(hv.z, w[4 * g + 2], acc);
                    acc = __fmaf_rn(hv.w, w[4 * g + 3], acc);
                }
                // groups 44..63 : k = 176..255 (transposed smem weights)
#pragma unroll
                for (int g = 0; g < NGS; ++g) {
                    float4 hv = h4[NGR + g];
                    float4 wv = wt4[g];
                    acc = __fmaf_rn(hv.x, wv.x, acc);
                    acc = __fmaf_rn(hv.y, wv.y, acc);
                    acc = __fmaf_rn(hv.z, wv.z, acc);
                    acc = __fmaf_rn(hv.w, wv.w, acc);
                }

                v = xla_tanh(__fadd_rn(acc, zx));
                const int nxt = cur ^ 1;
                smf[OFF_HBUF + nxt * D + gcol] = v;   // local publish
                nbar_arrive(NB_H, 256);
                st_remote_f32(nxt ? hb_r1 : hb_r0, v); // peer publish
                mbar_arrive_remote_rel(((t + 1) & 1) ? mb_r1 : mb_r0);
                __stcs(&yrow[(size_t)t * D], v);
                cur = nxt;
            }
            if (c < NCHUNK - 2) nbar_arrive(NB_EMPTY(c), 256);  // recycle slot
        }

        hfin[bb * D + gcol] = v;
    }

    // ALL threads: no CTA may exit while peer remote stores/arrives are in
    // flight toward this CTA's SMEM.
    cluster_sync_all();
}

// ---------------------------------------------------------------------------
extern "C" void kernel_launch(void* const* d_in, const int* in_sizes, int n_in,
                              void* d_out, int out_size)
{
    const float* input = (const float*)d_in[0];
    const float* h0    = (const float*)d_in[1];
    const float* W_h   = (const float*)d_in[2];
    const float* W_x   = (const float*)d_in[3];
    const float* b_h   = (const float*)d_in[4];
    const float* b_x   = (const float*)d_in[5];

    float* y    = (float*)d_out;
    float* hfin = y + (size_t)BATCH * SEQ * D;

    cudaFuncSetAttribute(rnn_cluster_kernel,
                         cudaFuncAttributeMaxDynamicSharedMemorySize,
                         SMEM_BYTES);

    rnn_cluster_kernel<<<2 * BATCH, 256, SMEM_BYTES>>>(
        input, h0, W_h, W_x, b_h, b_x, y, hfin);
}

// round 12
// speedup vs baseline: 1.2953x; 1.2953x over previous
#include <cuda_runtime.h>
#include <math.h>

#define BATCH 64
#define SEQ   2048
#define DIN   256
#define DOUT  256
#define MTOT  (BATCH * SEQ)

#define NSCAN   64
#define NWORK   64
#define NCTA    (NSCAN + NWORK)      // 128 CTAs, all wave-1 resident
#define CHUNK   64
#define NCHUNK  (SEQ / CHUNK)        // 32
#define NTILES  (NCHUNK * BATCH * 4) // 8192 64x64 tiles

#define KREG 192
#define KSM  (DOUT - KREG)           // 64
#define WSTRIDE 68                   // 17 float4/col: conflict-free (4*17j mod32)
#define SCAN_SMEM_FLOATS (DOUT * WSTRIDE + 2 * DOUT)
#define SMEM_BYTES (SCAN_SMEM_FLOATS * (int)sizeof(float))   // 71680

__device__ int g_flags[BATCH * NCHUNK];

__global__ void reset_flags_kernel()
{
    int i = blockIdx.x * blockDim.x + threadIdx.x;
    if (i < BATCH * NCHUNK) g_flags[i] = 0;
}

__device__ __forceinline__ int ld_acquire_gpu(const int* p)
{
    int v;
    asm volatile("ld.acquire.gpu.global.b32 %0, [%1];"
                 : "=r"(v) : "l"(p) : "memory");
    return v;
}

// ---------------------------------------------------------------------------
// Bit-exact replica of XLA's EmitFastTanh (Eigen fast tanh, FMA variant).
// ---------------------------------------------------------------------------
__device__ __forceinline__ float xla_tanh(float x)
{
    const float kClamp = 7.99881172180175781f;
    const float kTiny  = 0.0004f;
    const float a1  = 4.89352455891786e-03f;
    const float a3  = 6.37261928875436e-04f;
    const float a5  = 1.48572235717979e-05f;
    const float a7  = 5.12229709037114e-08f;
    const float a9  = -8.60467152213735e-11f;
    const float a11 = 2.00018790482477e-13f;
    const float a13 = -2.76076847742355e-16f;
    const float b0  = 4.89352518554385e-03f;
    const float b2  = 2.26843463243900e-03f;
    const float b4  = 1.18534705686654e-04f;
    const float b6  = 1.19825839466702e-06f;

    float ax = fabsf(x);
    float xc = fminf(fmaxf(x, -kClamp), kClamp);
    float x2 = __fmul_rn(xc, xc);

    float p = __fmaf_rn(x2, a13, a11);
    p = __fmaf_rn(x2, p, a9);
    p = __fmaf_rn(x2, p, a7);
    p = __fmaf_rn(x2, p, a5);
    p = __fmaf_rn(x2, p, a3);
    p = __fmaf_rn(x2, p, a1);
    p = __fmul_rn(xc, p);

    float q = __fmaf_rn(x2, b6, b4);
    q = __fmaf_rn(x2, q, b2);
    q = __fmaf_rn(x2, q, b0);

    float r = __fdiv_rn(p, q);
    return (ax < kTiny) ? x : r;
}

// ---------------------------------------------------------------------------
// GEMM producer: zx = input @ W_x + (b_x+b_h), 64x64 tiles in time order.
// zx stores use DEFAULT cache policy (consumer reads them ~5 chunks later).
// Bit-exact: single fp32 accumulator, ascending k, fused FMA.
// ---------------------------------------------------------------------------
__device__ void gemm_worker(
    float* sm, int worker,
    const float* __restrict__ A,
    const float* __restrict__ W,
    const float* __restrict__ b_h,
    const float* __restrict__ b_x,
    float* __restrict__ C)
{
    float* As   = sm;                // [64][36]
    float* Bs   = sm + 64 * 36;      // [32][64]
    float* bias = sm + 64 * 36 + 32 * 64;

    const int tid = threadIdx.x;
    const int tx = tid & 15;
    const int ty = tid >> 4;

    for (int tau = worker; tau < NTILES; tau += NWORK) {
        const int c  = tau >> 8;
        const int r  = tau & 255;
        const int bb = r >> 2;
        const int nq = r & 3;
        const long m0 = (long)bb * SEQ + (long)c * CHUNK;
        const int n0 = nq * 64;

        if (tid < 64) bias[tid] = __fadd_rn(b_h[n0 + tid], b_x[n0 + tid]);

        float acc[16];
#pragma unroll
        for (int i = 0; i < 16; ++i) acc[i] = 0.f;

        for (int kc = 0; kc < DIN; kc += 32) {
            __syncthreads();
            {
                int i0 = tid, i1 = tid + 256;
                int r0 = i0 >> 3, c0 = (i0 & 7) << 2;
                int r1 = i1 >> 3, c1 = (i1 & 7) << 2;
                float4 v0 = __ldcs((const float4*)(A + (m0 + r0) * DIN + kc + c0));
                float4 v1 = __ldcs((const float4*)(A + (m0 + r1) * DIN + kc + c1));
                As[r0 * 36 + c0 + 0] = v0.x; As[r0 * 36 + c0 + 1] = v0.y;
                As[r0 * 36 + c0 + 2] = v0.z; As[r0 * 36 + c0 + 3] = v0.w;
                As[r1 * 36 + c1 + 0] = v1.x; As[r1 * 36 + c1 + 1] = v1.y;
                As[r1 * 36 + c1 + 2] = v1.z; As[r1 * 36 + c1 + 3] = v1.w;
            }
            {
                int i0 = tid, i1 = tid + 256;
                int k0 = i0 >> 4, g0 = (i0 & 15) << 2;
                int k1 = i1 >> 4, g1 = (i1 & 15) << 2;
                *(float4*)(Bs + k0 * 64 + g0) =
                    *(const float4*)(W + (kc + k0) * DOUT + n0 + g0);
                *(float4*)(Bs + k1 * 64 + g1) =
                    *(const float4*)(W + (kc + k1) * DOUT + n0 + g1);
            }
            __syncthreads();

#pragma unroll
            for (int k = 0; k < 32; ++k) {
                float4 b4 = *(const float4*)(Bs + k * 64 + (tx << 2));
                float a0 = As[(ty * 4 + 0) * 36 + k];
                float a1 = As[(ty * 4 + 1) * 36 + k];
                float a2 = As[(ty * 4 + 2) * 36 + k];
                float a3 = As[(ty * 4 + 3) * 36 + k];
                acc[ 0] = __fmaf_rn(a0, b4.x, acc[ 0]);
                acc[ 1] = __fmaf_rn(a0, b4.y, acc[ 1]);
                acc[ 2] = __fmaf_rn(a0, b4.z, acc[ 2]);
                acc[ 3] = __fmaf_rn(a0, b4.w, acc[ 3]);
                acc[ 4] = __fmaf_rn(a1, b4.x, acc[ 4]);
                acc[ 5] = __fmaf_rn(a1, b4.y, acc[ 5]);
                acc[ 6] = __fmaf_rn(a1, b4.z, acc[ 6]);
                acc[ 7] = __fmaf_rn(a1, b4.w, acc[ 7]);
                acc[ 8] = __fmaf_rn(a2, b4.x, acc[ 8]);
                acc[ 9] = __fmaf_rn(a2, b4.y, acc[ 9]);
                acc[10] = __fmaf_rn(a2, b4.z, acc[10]);
                acc[11] = __fmaf_rn(a2, b4.w, acc[11]);
                acc[12] = __fmaf_rn(a3, b4.x, acc[12]);
                acc[13] = __fmaf_rn(a3, b4.y, acc[13]);
                acc[14] = __fmaf_rn(a3, b4.z, acc[14]);
                acc[15] = __fmaf_rn(a3, b4.w, acc[15]);
            }
        }

#pragma unroll
        for (int i = 0; i < 4; ++i) {
            float4 o;
            o.x = __fadd_rn(acc[i * 4 + 0], bias[(tx << 2) + 0]);
            o.y = __fadd_rn(acc[i * 4 + 1], bias[(tx << 2) + 1]);
            o.z = __fadd_rn(acc[i * 4 + 2], bias[(tx << 2) + 2]);
            o.w = __fadd_rn(acc[i * 4 + 3], bias[(tx << 2) + 3]);
            *(float4*)(C + (m0 + ty * 4 + i) * DOUT + n0 + (tx << 2)) = o;   // default policy
        }

        __threadfence();
        __syncthreads();
        if (tid == 0) atomicAdd(&g_flags[bb * NCHUNK + c], 1);
    }
}

// ---------------------------------------------------------------------------
// One scan step for buffer hc (read) -> hn (write). Strict single-accumulator
// ascending-k FMA chain, XLA tanh. Returns the new h value for this column.
// ---------------------------------------------------------------------------
__device__ __forceinline__ float scan_step(
    const float4* __restrict__ h4,
    const float* __restrict__ w,
    const float4* __restrict__ wt4,
    float zx)
{
    float acc = 0.f;
#pragma unroll
    for (int g = 0; g < KREG / 4; ++g) {
        float4 hv = h4[g];
        acc = __fmaf_rn(hv.x, w[4 * g + 0], acc);
        acc = __fmaf_rn(hv.y, w[4 * g + 1], acc);
        acc = __fmaf_rn(hv.z, w[4 * g + 2], acc);
        acc = __fmaf_rn(hv.w, w[4 * g + 3], acc);
    }
#pragma unroll
    for (int g = 0; g < KSM / 4; ++g) {
        float4 hv = h4[(KREG >> 2) + g];
        float4 wv = wt4[g];
        acc = __fmaf_rn(hv.x, wv.x, acc);
        acc = __fmaf_rn(hv.y, wv.y, acc);
        acc = __fmaf_rn(hv.z, wv.z, acc);
        acc = __fmaf_rn(hv.w, wv.w, acc);
    }
    return xla_tanh(__fadd_rn(acc, zx));
}

// ---------------------------------------------------------------------------
// Fused kernel. Scan CTAs [0,64): thread j owns column j. Round-6 proven
// structure; step loop hand-unrolled by 2 with explicit ping/pong buffers.
// ---------------------------------------------------------------------------
__global__ __launch_bounds__(256, 1) void rnn_fused_kernel(
    const float* __restrict__ input,
    const float* __restrict__ h0,
    const float* __restrict__ Wh,
    const float* __restrict__ Wx,
    const float* __restrict__ b_h,
    const float* __restrict__ b_x,
    float* __restrict__ y,
    float* __restrict__ hfin)
{
    extern __shared__ float sm[];

    if (blockIdx.x >= NSCAN) {
        gemm_worker(sm, blockIdx.x - NSCAN, input, Wx, b_h, b_x, y);
        return;
    }

    float* WsT  = sm;                     // [DOUT][WSTRIDE]
    float* hb0  = sm + DOUT * WSTRIDE;    // buffer 0
    float* hb1  = hb0 + DOUT;             // buffer 1

    const int b = blockIdx.x;
    const int j = threadIdx.x;

    float w[KREG];
#pragma unroll
    for (int kk = 0; kk < KREG; ++kk)
        w[kk] = Wh[kk * DOUT + j];

#pragma unroll
    for (int i = 0; i < KSM; ++i)
        WsT[j * WSTRIDE + i] = Wh[(KREG + i) * DOUT + j];

    hb0[j] = h0[b * DOUT + j];

    float* yb = y + (size_t)b * SEQ * DOUT;
    const float4* wt4 = (const float4*)(WsT + j * WSTRIDE);
    const float4* h40 = (const float4*)hb0;
    const float4* h41 = (const float4*)hb1;

    for (int c = 0; c < NCHUNK; ++c) {
        if (j == 0) {
            while (ld_acquire_gpu(&g_flags[b * NCHUNK + c]) != 4) { }
        }
        __syncthreads();                  // chunk gate; also orders setup at c=0

#pragma unroll 1
        for (int ti = 0; ti < CHUNK; ti += 2) {
            const size_t t0 = (size_t)(c * CHUNK + ti) * DOUT + j;

            // step even: hb0 -> hb1
            float zx0 = __ldcs(&yb[t0]);
            float v0 = scan_step(h40, w, wt4, zx0);
            hb1[j] = v0;
            __stcs(&yb[t0], v0);
            __syncthreads();

            // step odd: hb1 -> hb0
            float zx1 = __ldcs(&yb[t0 + DOUT]);
            float v1 = scan_step(h41, w, wt4, zx1);
            hb0[j] = v1;
            __stcs(&yb[t0 + DOUT], v1);
            __syncthreads();
        }
    }

    hfin[b * DOUT + j] = hb0[j];          // SEQ even: final state in hb0
}

// ---------------------------------------------------------------------------
extern "C" void kernel_launch(void* const* d_in, const int* in_sizes, int n_in,
                              void* d_out, int out_size)
{
    const float* input = (const float*)d_in[0];
    const float* h0    = (const float*)d_in[1];
    const float* W_h   = (const float*)d_in[2];
    const float* W_x   = (const float*)d_in[3];
    const float* b_h   = (const float*)d_in[4];
    const float* b_x   = (const float*)d_in[5];

    float* y    = (float*)d_out;
    float* hfin = y + (size_t)BATCH * SEQ * DOUT;

    cudaFuncSetAttribute(rnn_fused_kernel,
                         cudaFuncAttributeMaxDynamicSharedMemorySize,
                         SMEM_BYTES);

    reset_flags_kernel<<<8, 256>>>();
    rnn_fused_kernel<<<NCTA, 256, SMEM_BYTES>>>(
        input, h0, W_h, W_x, b_h, b_x, y, hfin);
}

// round 13
// speedup vs baseline: 1.2955x; 1.0001x over previous
#include <cuda_runtime.h>
#include <math.h>

#define BATCH 64
#define SEQ   2048
#define DIN   256
#define DOUT  256
#define MTOT  (BATCH * SEQ)

#define NSCAN   64
#define NWORK   84
#define NCTA    (NSCAN + NWORK)      // 148 CTAs = one per SM
#define CHUNK   64
#define NCHUNK  (SEQ / CHUNK)        // 32
#define NTILES  (NCHUNK * BATCH * 4) // 8192 64x64 tiles, time-ordered

#define KREG 192
#define KSM  (DOUT - KREG)           // 64
#define WSTRIDE 68                   // 17 float4/col: conflict-free
#define SCAN_SMEM_FLOATS (DOUT * WSTRIDE + 2 * DOUT)
#define SMEM_BYTES (SCAN_SMEM_FLOATS * (int)sizeof(float))   // 71680

__device__ int g_flags[BATCH * NCHUNK];

__global__ void reset_flags_kernel()
{
    int i = blockIdx.x * blockDim.x + threadIdx.x;
    if (i < BATCH * NCHUNK) g_flags[i] = 0;
}

__device__ __forceinline__ int ld_acquire_gpu(const int* p)
{
    int v;
    asm volatile("ld.acquire.gpu.global.b32 %0, [%1];"
                 : "=r"(v) : "l"(p) : "memory");
    return v;
}

// ---------------------------------------------------------------------------
// Bit-exact replica of XLA's EmitFastTanh (Eigen fast tanh, FMA variant).
// ---------------------------------------------------------------------------
__device__ __forceinline__ float xla_tanh(float x)
{
    const float kClamp = 7.99881172180175781f;
    const float kTiny  = 0.0004f;
    const float a1  = 4.89352455891786e-03f;
    const float a3  = 6.37261928875436e-04f;
    const float a5  = 1.48572235717979e-05f;
    const float a7  = 5.12229709037114e-08f;
    const float a9  = -8.60467152213735e-11f;
    const float a11 = 2.00018790482477e-13f;
    const float a13 = -2.76076847742355e-16f;
    const float b0  = 4.89352518554385e-03f;
    const float b2  = 2.26843463243900e-03f;
    const float b4  = 1.18534705686654e-04f;
    const float b6  = 1.19825839466702e-06f;

    float ax = fabsf(x);
    float xc = fminf(fmaxf(x, -kClamp), kClamp);
    float x2 = __fmul_rn(xc, xc);

    float p = __fmaf_rn(x2, a13, a11);
    p = __fmaf_rn(x2, p, a9);
    p = __fmaf_rn(x2, p, a7);
    p = __fmaf_rn(x2, p, a5);
    p = __fmaf_rn(x2, p, a3);
    p = __fmaf_rn(x2, p, a1);
    p = __fmul_rn(xc, p);

    float q = __fmaf_rn(x2, b6, b4);
    q = __fmaf_rn(x2, q, b2);
    q = __fmaf_rn(x2, q, b0);

    float r = __fdiv_rn(p, q);
    return (ax < kTiny) ? x : r;
}

// ---------------------------------------------------------------------------
// GEMM producer: zx = input @ W_x + (b_x+b_h), 64x64 tiles in time order.
// zx stores use DEFAULT cache policy (consumer reads them a few chunks later).
// Bit-exact: single fp32 accumulator, ascending k, fused FMA.
// ---------------------------------------------------------------------------
__device__ void gemm_worker(
    float* sm, int worker,
    const float* __restrict__ A,
    const float* __restrict__ W,
    const float* __restrict__ b_h,
    const float* __restrict__ b_x,
    float* __restrict__ C)
{
    float* As   = sm;                // [64][36]
    float* Bs   = sm + 64 * 36;      // [32][64]
    float* bias = sm + 64 * 36 + 32 * 64;

    const int tid = threadIdx.x;
    const int tx = tid & 15;
    const int ty = tid >> 4;

    for (int tau = worker; tau < NTILES; tau += NWORK) {
        const int c  = tau >> 8;
        const int r  = tau & 255;
        const int bb = r >> 2;
        const int nq = r & 3;
        const long m0 = (long)bb * SEQ + (long)c * CHUNK;
        const int n0 = nq * 64;

        if (tid < 64) bias[tid] = __fadd_rn(b_h[n0 + tid], b_x[n0 + tid]);

        float acc[16];
#pragma unroll
        for (int i = 0; i < 16; ++i) acc[i] = 0.f;

        for (int kc = 0; kc < DIN; kc += 32) {
            __syncthreads();
            {
                int i0 = tid, i1 = tid + 256;
                int r0 = i0 >> 3, c0 = (i0 & 7) << 2;
                int r1 = i1 >> 3, c1 = (i1 & 7) << 2;
                float4 v0 = __ldcs((const float4*)(A + (m0 + r0) * DIN + kc + c0));
                float4 v1 = __ldcs((const float4*)(A + (m0 + r1) * DIN + kc + c1));
                As[r0 * 36 + c0 + 0] = v0.x; As[r0 * 36 + c0 + 1] = v0.y;
                As[r0 * 36 + c0 + 2] = v0.z; As[r0 * 36 + c0 + 3] = v0.w;
                As[r1 * 36 + c1 + 0] = v1.x; As[r1 * 36 + c1 + 1] = v1.y;
                As[r1 * 36 + c1 + 2] = v1.z; As[r1 * 36 + c1 + 3] = v1.w;
            }
            {
                int i0 = tid, i1 = tid + 256;
                int k0 = i0 >> 4, g0 = (i0 & 15) << 2;
                int k1 = i1 >> 4, g1 = (i1 & 15) << 2;
                *(float4*)(Bs + k0 * 64 + g0) =
                    *(const float4*)(W + (kc + k0) * DOUT + n0 + g0);
                *(float4*)(Bs + k1 * 64 + g1) =
                    *(const float4*)(W + (kc + k1) * DOUT + n0 + g1);
            }
            __syncthreads();

#pragma unroll
            for (int k = 0; k < 32; ++k) {
                float4 b4 = *(const float4*)(Bs + k * 64 + (tx << 2));
                float a0 = As[(ty * 4 + 0) * 36 + k];
                float a1 = As[(ty * 4 + 1) * 36 + k];
                float a2 = As[(ty * 4 + 2) * 36 + k];
                float a3 = As[(ty * 4 + 3) * 36 + k];
                acc[ 0] = __fmaf_rn(a0, b4.x, acc[ 0]);
                acc[ 1] = __fmaf_rn(a0, b4.y, acc[ 1]);
                acc[ 2] = __fmaf_rn(a0, b4.z, acc[ 2]);
                acc[ 3] = __fmaf_rn(a0, b4.w, acc[ 3]);
                acc[ 4] = __fmaf_rn(a1, b4.x, acc[ 4]);
                acc[ 5] = __fmaf_rn(a1, b4.y, acc[ 5]);
                acc[ 6] = __fmaf_rn(a1, b4.z, acc[ 6]);
                acc[ 7] = __fmaf_rn(a1, b4.w, acc[ 7]);
                acc[ 8] = __fmaf_rn(a2, b4.x, acc[ 8]);
                acc[ 9] = __fmaf_rn(a2, b4.y, acc[ 9]);
                acc[10] = __fmaf_rn(a2, b4.z, acc[10]);
                acc[11] = __fmaf_rn(a2, b4.w, acc[11]);
                acc[12] = __fmaf_rn(a3, b4.x, acc[12]);
                acc[13] = __fmaf_rn(a3, b4.y, acc[13]);
                acc[14] = __fmaf_rn(a3, b4.z, acc[14]);
                acc[15] = __fmaf_rn(a3, b4.w, acc[15]);
            }
        }

#pragma unroll
        for (int i = 0; i < 4; ++i) {
            float4 o;
            o.x = __fadd_rn(acc[i * 4 + 0], bias[(tx << 2) + 0]);
            o.y = __fadd_rn(acc[i * 4 + 1], bias[(tx << 2) + 1]);
            o.z = __fadd_rn(acc[i * 4 + 2], bias[(tx << 2) + 2]);
            o.w = __fadd_rn(acc[i * 4 + 3], bias[(tx << 2) + 3]);
            *(float4*)(C + (m0 + ty * 4 + i) * DOUT + n0 + (tx << 2)) = o;
        }

        __threadfence();
        __syncthreads();
        if (tid == 0) atomicAdd(&g_flags[bb * NCHUNK + c], 1);
    }
}

// ---------------------------------------------------------------------------
// One scan step: strict single-accumulator ascending-k FMA chain + XLA tanh.
// ---------------------------------------------------------------------------
__device__ __forceinline__ float scan_step(
    const float4* __restrict__ h4,
    const float* __restrict__ w,
    const float4* __restrict__ wt4,
    float zx)
{
    float acc = 0.f;
#pragma unroll
    for (int g = 0; g < KREG / 4; ++g) {
        float4 hv = h4[g];
        acc = __fmaf_rn(hv.x, w[4 * g + 0], acc);
        acc = __fmaf_rn(hv.y, w[4 * g + 1], acc);
        acc = __fmaf_rn(hv.z, w[4 * g + 2], acc);
        acc = __fmaf_rn(hv.w, w[4 * g + 3], acc);
    }
#pragma unroll
    for (int g = 0; g < KSM / 4; ++g) {
        float4 hv = h4[(KREG >> 2) + g];
        float4 wv = wt4[g];
        acc = __fmaf_rn(hv.x, wv.x, acc);
        acc = __fmaf_rn(hv.y, wv.y, acc);
        acc = __fmaf_rn(hv.z, wv.z, acc);
        acc = __fmaf_rn(hv.w, wv.w, acc);
    }
    return xla_tanh(__fadd_rn(acc, zx));
}

// ---------------------------------------------------------------------------
// Fused kernel. Scan CTAs [0,64): thread j owns column j; step loop unrolled
// by 2 with explicit ping/pong buffers; BOTH zx loads hoisted to pair start.
// ---------------------------------------------------------------------------
__global__ __launch_bounds__(256, 1) void rnn_fused_kernel(
    const float* __restrict__ input,
    const float* __restrict__ h0,
    const float* __restrict__ Wh,
    const float* __restrict__ Wx,
    const float* __restrict__ b_h,
    const float* __restrict__ b_x,
    float* __restrict__ y,
    float* __restrict__ hfin)
{
    extern __shared__ float sm[];

    if (blockIdx.x >= NSCAN) {
        gemm_worker(sm, blockIdx.x - NSCAN, input, Wx, b_h, b_x, y);
        return;
    }

    float* WsT  = sm;                     // [DOUT][WSTRIDE]
    float* hb0  = sm + DOUT * WSTRIDE;    // buffer 0
    float* hb1  = hb0 + DOUT;             // buffer 1

    const int b = blockIdx.x;
    const int j = threadIdx.x;

    float w[KREG];
#pragma unroll
    for (int kk = 0; kk < KREG; ++kk)
        w[kk] = Wh[kk * DOUT + j];

#pragma unroll
    for (int i = 0; i < KSM; ++i)
        WsT[j * WSTRIDE + i] = Wh[(KREG + i) * DOUT + j];

    hb0[j] = h0[b * DOUT + j];

    float* yb = y + (size_t)b * SEQ * DOUT;
    const float4* wt4 = (const float4*)(WsT + j * WSTRIDE);
    const float4* h40 = (const float4*)hb0;
    const float4* h41 = (const float4*)hb1;

    for (int c = 0; c < NCHUNK; ++c) {
        if (j == 0) {
            while (ld_acquire_gpu(&g_flags[b * NCHUNK + c]) != 4) { }
        }
        __syncthreads();                  // chunk gate; also orders setup at c=0

#pragma unroll 1
        for (int ti = 0; ti < CHUNK; ti += 2) {
            const size_t t0 = (size_t)(c * CHUNK + ti) * DOUT + j;

            // both zx loads issued up front: zx1 gets ~2 chains of cover
            float zx0 = __ldcs(&yb[t0]);
            float zx1 = __ldcs(&yb[t0 + DOUT]);

            // step even: hb0 -> hb1
            float v0 = scan_step(h40, w, wt4, zx0);
            hb1[j] = v0;
            __stcs(&yb[t0], v0);
            __syncthreads();

            // step odd: hb1 -> hb0
            float v1 = scan_step(h41, w, wt4, zx1);
            hb0[j] = v1;
            __stcs(&yb[t0 + DOUT], v1);
            __syncthreads();
        }
    }

    hfin[b * DOUT + j] = hb0[j];          // SEQ even: final state in hb0
}

// ---------------------------------------------------------------------------
extern "C" void kernel_launch(void* const* d_in, const int* in_sizes, int n_in,
                              void* d_out, int out_size)
{
    const float* input = (const float*)d_in[0];
    const float* h0    = (const float*)d_in[1];
    const float* W_h   = (const float*)d_in[2];
    const float* W_x   = (const float*)d_in[3];
    const float* b_h   = (const float*)d_in[4];
    const float* b_x   = (const float*)d_in[5];

    float* y    = (float*)d_out;
    float* hfin = y + (size_t)BATCH * SEQ * DOUT;

    cudaFuncSetAttribute(rnn_fused_kernel,
                         cudaFuncAttributeMaxDynamicSharedMemorySize,
                         SMEM_BYTES);

    reset_flags_kernel<<<8, 256>>>();
    rnn_fused_kernel<<<NCTA, 256, SMEM_BYTES>>>(
        input, h0, W_h, W_x, b_h, b_x, y, hfin);
}